// round 11
// baseline (speedup 1.0000x reference)
#include <cuda_runtime.h>

// Problem dims
#define T_DIM 2048
#define B_DIM 16
#define D_DIM 1024
#define N_DIM 64
#define C_DIM 256   // 4*N

#define NUM_GEMM_CTAS 168
#define NUM_SCAN_CTAS 128
#define NUM_MTILES    256          // (T*B)/128 m-tiles; each = 8 timesteps
#define NUM_TILES     512          // 256 m-tiles x 2 n-tiles

// 32 MB scratch for projected k/v/q/m: (T, B, 4N)
__device__ float g_kvqm[(size_t)T_DIM * B_DIM * C_DIM];
// Per-m-tile completion counters (2 = both n-tiles done)
__device__ int g_done[NUM_MTILES];

__global__ void e80_zero_flags() {
    g_done[threadIdx.x] = 0;
}

// ---------------------------------------------------------------------------
// GEMM tile body: computes one 128x128 tile of kvqm = X * W^T (NT, fp32).
// ---------------------------------------------------------------------------
__device__ __forceinline__ void gemm_tile(const float* __restrict__ A,
                                          const float* __restrict__ W,
                                          int mBase, int nBase,
                                          float (*As)[128], float (*Bs)[128]) {
    const int K  = D_DIM;
    const int tid = threadIdx.x;
    const int lr = tid >> 2;          // 0..63 (and +64)
    const int kq = (tid & 3) * 4;     // 0,4,8,12

    const float* Ag = A + (size_t)(mBase + lr) * K + kq;
    const float* Wg = W + (size_t)(nBase + lr) * K + kq;

    float4 pa0 = *(const float4*)(Ag);
    float4 pa1 = *(const float4*)(Ag + (size_t)64 * K);
    float4 pb0 = *(const float4*)(Wg);
    float4 pb1 = *(const float4*)(Wg + (size_t)64 * K);

    const int tx = tid & 15;
    const int ty = tid >> 4;

    float acc[8][8];
#pragma unroll
    for (int i = 0; i < 8; i++)
#pragma unroll
        for (int j = 0; j < 8; j++) acc[i][j] = 0.0f;

    for (int k0 = 0; k0 < K; k0 += 16) {
        As[kq + 0][lr] = pa0.x; As[kq + 1][lr] = pa0.y;
        As[kq + 2][lr] = pa0.z; As[kq + 3][lr] = pa0.w;
        As[kq + 0][lr + 64] = pa1.x; As[kq + 1][lr + 64] = pa1.y;
        As[kq + 2][lr + 64] = pa1.z; As[kq + 3][lr + 64] = pa1.w;
        Bs[kq + 0][lr] = pb0.x; Bs[kq + 1][lr] = pb0.y;
        Bs[kq + 2][lr] = pb0.z; Bs[kq + 3][lr] = pb0.w;
        Bs[kq + 0][lr + 64] = pb1.x; Bs[kq + 1][lr + 64] = pb1.y;
        Bs[kq + 2][lr + 64] = pb1.z; Bs[kq + 3][lr + 64] = pb1.w;
        __syncthreads();

        if (k0 + 16 < K) {
            pa0 = *(const float4*)(Ag + k0 + 16);
            pa1 = *(const float4*)(Ag + (size_t)64 * K + k0 + 16);
            pb0 = *(const float4*)(Wg + k0 + 16);
            pb1 = *(const float4*)(Wg + (size_t)64 * K + k0 + 16);
        }

#pragma unroll
        for (int k = 0; k < 16; k++) {
            float ar[8], br[8];
            *(float4*)&ar[0] = *(const float4*)&As[k][ty * 8];
            *(float4*)&ar[4] = *(const float4*)&As[k][ty * 8 + 4];
            *(float4*)&br[0] = *(const float4*)&Bs[k][tx * 8];
            *(float4*)&br[4] = *(const float4*)&Bs[k][tx * 8 + 4];
#pragma unroll
            for (int i = 0; i < 8; i++)
#pragma unroll
                for (int j = 0; j < 8; j++)
                    acc[i][j] = fmaf(ar[i], br[j], acc[i][j]);
        }
        __syncthreads();
    }

#pragma unroll
    for (int i = 0; i < 8; i++) {
        float* Cp = g_kvqm + (size_t)(mBase + ty * 8 + i) * C_DIM + nBase + tx * 8;
        *(float4*)Cp       = make_float4(acc[i][0], acc[i][1], acc[i][2], acc[i][3]);
        *(float4*)(Cp + 4) = make_float4(acc[i][4], acc[i][5], acc[i][6], acc[i][7]);
    }
}

__device__ __forceinline__ float warp_sum(float p) {
#pragma unroll
    for (int off = 16; off > 0; off >>= 1)
        p += __shfl_xor_sync(0xffffffffu, p, off);
    return p;
}

// Consumer-side chunk wait (chunk m ready when both n-tiles committed).
__device__ __forceinline__ void wait_chunk(int m) {
    if (*(volatile int*)&g_done[m] < 2) {
        while (*(volatile int*)&g_done[m] < 2) __nanosleep(64);
    }
    __threadfence();   // acquire: order subsequent kvqm loads after flag
}

// ---------------------------------------------------------------------------
// Fused kernel: blocks [0, NUM_GEMM_CTAS) produce kvqm tiles in time order;
// blocks [NUM_GEMM_CTAS, +NUM_SCAN_CTAS) run the gated scan, consuming
// 8-timestep chunks as they become ready. Producers never wait on consumers,
// so the kernel is deadlock-free even if co-residency degrades.
// ---------------------------------------------------------------------------
__global__ __launch_bounds__(256, 2)
void e80_fused(const float* __restrict__ x,
               const float* __restrict__ S0,
               const float* __restrict__ M0,
               const float* __restrict__ W,
               const float* __restrict__ B_S,
               const float* __restrict__ B_M,
               float* __restrict__ out, int out_size) {
    __shared__ float As[16][128];
    __shared__ float Bs[16][128];

    if (blockIdx.x < NUM_GEMM_CTAS) {
        // ---------------- producer: persistent GEMM ----------------
        for (int L = blockIdx.x; L < NUM_TILES; L += NUM_GEMM_CTAS) {
            const int m = L >> 1;          // time-major: tiles ordered by m
            const int n = L & 1;
            gemm_tile(x, W, m * 128, n * 128, As, Bs);
            __threadfence();               // make tile stores visible (gpu scope)
            __syncthreads();               // all threads' stores + fences done
            if (threadIdx.x == 0) atomicAdd(&g_done[m], 1);
            __syncthreads();               // smem reuse safety for next tile
        }
        return;
    }

    // ---------------- consumer: gated two-level scan ----------------
    const int warp = threadIdx.x >> 5;
    const int lane = threadIdx.x & 31;
    const int row  = (blockIdx.x - NUM_GEMM_CTAS) * 8 + warp;   // 0..1023
    const int b    = row >> 6;
    const int i    = row & 63;

    float2 bs2 = ((const float2*)(B_S + i * N_DIM))[lane];
    float2 bm2 = ((const float2*)(B_M + i * N_DIM))[lane];
    float2 s   = ((const float2*)(S0 + (size_t)row * N_DIM))[lane];
    float2 ms  = ((const float2*)(M0 + (size_t)row * N_DIM))[lane];

    // Wait for chunk 0, then load t = 0 inputs
    wait_chunk(0);
    const float* p0 = g_kvqm + b * C_DIM;
    float2 k2 = ((const float2*)(p0      ))[lane];
    float2 q2 = ((const float2*)(p0 + 128))[lane];
    float2 m2 = ((const float2*)(p0 + 192))[lane];
    float  v  = p0[64 + i];

    for (int t = 0; t < T_DIM; t++) {
        // ---- prefetch t+1 (wait at chunk boundary only) ----
        const int tn = (t + 1 < T_DIM) ? (t + 1) : t;
        if (tn != t && (tn & 7) == 0) wait_chunk(tn >> 3);
        const float* pn = g_kvqm + (size_t)tn * (B_DIM * C_DIM) + b * C_DIM;
        float2 nk = ((const float2*)(pn      ))[lane];
        float2 nq = ((const float2*)(pn + 128))[lane];
        float2 nm = ((const float2*)(pn + 192))[lane];
        float  nv = pn[64 + i];

        // ---- S gate: G_S = sigmoid(v_i*k_j + B_S) ----
        float vk0 = v * k2.x, vk1 = v * k2.y;
        float x0 = fmaxf(vk0 + bs2.x, -30.0f);
        float x1 = fmaxf(vk1 + bs2.y, -30.0f);
        float e0 = __expf(-x0), e1 = __expf(-x1);
        float d0 = 1.0f + e0,   d1 = 1.0f + e1;
        float r  = __fdividef(1.0f, d0 * d1);   // 1 RCP serves 2 sigmoids
        float g0 = r * d1,      g1 = r * d0;
        s.x = fmaf(g0, s.x - vk0, vk0);
        s.y = fmaf(g1, s.y - vk1, vk1);

        // ---- Sq = S @ q (warp allreduce over 64 cols) ----
        float Sq = warp_sum(fmaf(s.x, q2.x, s.y * q2.y));

        // ---- M gate ----
        float sm0 = Sq * m2.x, sm1 = Sq * m2.y;
        float y0 = fmaxf(sm0 + bm2.x, -30.0f);
        float y1 = fmaxf(sm1 + bm2.y, -30.0f);
        float f0 = __expf(-y0), f1 = __expf(-y1);
        float c0 = 1.0f + f0,   c1 = 1.0f + f1;
        float rr = __fdividef(1.0f, c0 * c1);
        float h0 = rr * c1,     h1 = rr * c0;
        ms.x = fmaf(h0, ms.x - sm0, sm0);
        ms.y = fmaf(h1, ms.y - sm1, sm1);

        // ---- out = M @ q ----
        float o = warp_sum(fmaf(ms.x, q2.x, ms.y * q2.y));
        if (lane == 0)
            out[(size_t)(t * B_DIM + b) * N_DIM + i] = o;

        k2 = nk; q2 = nq; m2 = nm; v = nv;
    }

    // Final states S_f, M_f packed after outs
    const int OUTS = T_DIM * B_DIM * N_DIM;
    const int STN  = B_DIM * N_DIM * N_DIM;
    if (out_size >= OUTS + 2 * STN) {
        ((float2*)(out + OUTS + (size_t)row * N_DIM))[lane]       = s;
        ((float2*)(out + OUTS + STN + (size_t)row * N_DIM))[lane] = ms;
    }
}

// ---------------------------------------------------------------------------
// Launch
// ---------------------------------------------------------------------------
extern "C" void kernel_launch(void* const* d_in, const int* in_sizes, int n_in,
                              void* d_out, int out_size) {
    const float* x   = (const float*)d_in[0];   // (T, B, D)
    const float* S0  = (const float*)d_in[1];   // (B, N, N)
    const float* M0  = (const float*)d_in[2];   // (B, N, N)
    const float* W   = (const float*)d_in[3];   // (4N, D)
    const float* B_S = (const float*)d_in[4];   // (N, N)
    const float* B_M = (const float*)d_in[5];   // (N, N)
    float* out = (float*)d_out;

    e80_zero_flags<<<1, NUM_MTILES>>>();
    e80_fused<<<NUM_GEMM_CTAS + NUM_SCAN_CTAS, 256>>>(
        x, S0, M0, W, B_S, B_M, out, out_size);
}

// round 12
// speedup vs baseline: 1.0002x; 1.0002x over previous
#include <cuda_runtime.h>

// Problem dims
#define T_DIM 2048
#define B_DIM 16
#define D_DIM 1024
#define N_DIM 64
#define C_DIM 256   // 4*N

#define NUM_GEMM_CTAS 168
#define NUM_SCAN_CTAS 128
#define NUM_MTILES    256          // (T*B)/128 m-tiles; each = 8 timesteps
#define NUM_TILES     512          // 256 m-tiles x 2 n-tiles

// 32 MB scratch for projected k/v/q/m: (T, B, 4N)
__device__ float g_kvqm[(size_t)T_DIM * B_DIM * C_DIM];
// Per-m-tile completion counters (2 = both n-tiles done)
__device__ int g_done[NUM_MTILES];

__global__ void e80_zero_flags() {
    g_done[threadIdx.x] = 0;
}

// ---------------------------------------------------------------------------
// GEMM tile body: computes one 128x128 tile of kvqm = X * W^T (NT, fp32).
// ---------------------------------------------------------------------------
__device__ __forceinline__ void gemm_tile(const float* __restrict__ A,
                                          const float* __restrict__ W,
                                          int mBase, int nBase,
                                          float (*As)[128], float (*Bs)[128]) {
    const int K  = D_DIM;
    const int tid = threadIdx.x;
    const int lr = tid >> 2;          // 0..63 (and +64)
    const int kq = (tid & 3) * 4;     // 0,4,8,12

    const float* Ag = A + (size_t)(mBase + lr) * K + kq;
    const float* Wg = W + (size_t)(nBase + lr) * K + kq;

    float4 pa0 = *(const float4*)(Ag);
    float4 pa1 = *(const float4*)(Ag + (size_t)64 * K);
    float4 pb0 = *(const float4*)(Wg);
    float4 pb1 = *(const float4*)(Wg + (size_t)64 * K);

    const int tx = tid & 15;
    const int ty = tid >> 4;

    float acc[8][8];
#pragma unroll
    for (int i = 0; i < 8; i++)
#pragma unroll
        for (int j = 0; j < 8; j++) acc[i][j] = 0.0f;

    for (int k0 = 0; k0 < K; k0 += 16) {
        As[kq + 0][lr] = pa0.x; As[kq + 1][lr] = pa0.y;
        As[kq + 2][lr] = pa0.z; As[kq + 3][lr] = pa0.w;
        As[kq + 0][lr + 64] = pa1.x; As[kq + 1][lr + 64] = pa1.y;
        As[kq + 2][lr + 64] = pa1.z; As[kq + 3][lr + 64] = pa1.w;
        Bs[kq + 0][lr] = pb0.x; Bs[kq + 1][lr] = pb0.y;
        Bs[kq + 2][lr] = pb0.z; Bs[kq + 3][lr] = pb0.w;
        Bs[kq + 0][lr + 64] = pb1.x; Bs[kq + 1][lr + 64] = pb1.y;
        Bs[kq + 2][lr + 64] = pb1.z; Bs[kq + 3][lr + 64] = pb1.w;
        __syncthreads();

        if (k0 + 16 < K) {
            pa0 = *(const float4*)(Ag + k0 + 16);
            pa1 = *(const float4*)(Ag + (size_t)64 * K + k0 + 16);
            pb0 = *(const float4*)(Wg + k0 + 16);
            pb1 = *(const float4*)(Wg + (size_t)64 * K + k0 + 16);
        }

#pragma unroll
        for (int k = 0; k < 16; k++) {
            float ar[8], br[8];
            *(float4*)&ar[0] = *(const float4*)&As[k][ty * 8];
            *(float4*)&ar[4] = *(const float4*)&As[k][ty * 8 + 4];
            *(float4*)&br[0] = *(const float4*)&Bs[k][tx * 8];
            *(float4*)&br[4] = *(const float4*)&Bs[k][tx * 8 + 4];
#pragma unroll
            for (int i = 0; i < 8; i++)
#pragma unroll
                for (int j = 0; j < 8; j++)
                    acc[i][j] = fmaf(ar[i], br[j], acc[i][j]);
        }
        __syncthreads();
    }

#pragma unroll
    for (int i = 0; i < 8; i++) {
        float* Cp = g_kvqm + (size_t)(mBase + ty * 8 + i) * C_DIM + nBase + tx * 8;
        *(float4*)Cp       = make_float4(acc[i][0], acc[i][1], acc[i][2], acc[i][3]);
        *(float4*)(Cp + 4) = make_float4(acc[i][4], acc[i][5], acc[i][6], acc[i][7]);
    }
}

__device__ __forceinline__ float warp_sum(float p) {
#pragma unroll
    for (int off = 16; off > 0; off >>= 1)
        p += __shfl_xor_sync(0xffffffffu, p, off);
    return p;
}

// Consumer-side chunk wait (chunk m ready when both n-tiles committed).
__device__ __forceinline__ void wait_chunk(int m) {
    if (*(volatile int*)&g_done[m] < 2) {
        while (*(volatile int*)&g_done[m] < 2) __nanosleep(64);
    }
    __threadfence();   // acquire: order subsequent kvqm loads after flag
}

// ---------------------------------------------------------------------------
// Fused kernel: blocks [0, NUM_GEMM_CTAS) produce kvqm tiles in time order;
// blocks [NUM_GEMM_CTAS, +NUM_SCAN_CTAS) run the gated scan, consuming
// 8-timestep chunks as they become ready. Producers never wait on consumers,
// so the kernel is deadlock-free even if co-residency degrades.
// ---------------------------------------------------------------------------
__global__ __launch_bounds__(256, 2)
void e80_fused(const float* __restrict__ x,
               const float* __restrict__ S0,
               const float* __restrict__ M0,
               const float* __restrict__ W,
               const float* __restrict__ B_S,
               const float* __restrict__ B_M,
               float* __restrict__ out, int out_size) {
    __shared__ float As[16][128];
    __shared__ float Bs[16][128];

    if (blockIdx.x < NUM_GEMM_CTAS) {
        // ---------------- producer: persistent GEMM ----------------
        for (int L = blockIdx.x; L < NUM_TILES; L += NUM_GEMM_CTAS) {
            const int m = L >> 1;          // time-major: tiles ordered by m
            const int n = L & 1;
            gemm_tile(x, W, m * 128, n * 128, As, Bs);
            __threadfence();               // make tile stores visible (gpu scope)
            __syncthreads();               // all threads' stores + fences done
            if (threadIdx.x == 0) atomicAdd(&g_done[m], 1);
            __syncthreads();               // smem reuse safety for next tile
        }
        return;
    }

    // ---------------- consumer: gated two-level scan ----------------
    const int warp = threadIdx.x >> 5;
    const int lane = threadIdx.x & 31;
    const int row  = (blockIdx.x - NUM_GEMM_CTAS) * 8 + warp;   // 0..1023
    const int b    = row >> 6;
    const int i    = row & 63;

    float2 bs2 = ((const float2*)(B_S + i * N_DIM))[lane];
    float2 bm2 = ((const float2*)(B_M + i * N_DIM))[lane];
    float2 s   = ((const float2*)(S0 + (size_t)row * N_DIM))[lane];
    float2 ms  = ((const float2*)(M0 + (size_t)row * N_DIM))[lane];

    // Wait for chunk 0, then load t = 0 inputs
    wait_chunk(0);
    const float* p0 = g_kvqm + b * C_DIM;
    float2 k2 = ((const float2*)(p0      ))[lane];
    float2 q2 = ((const float2*)(p0 + 128))[lane];
    float2 m2 = ((const float2*)(p0 + 192))[lane];
    float  v  = p0[64 + i];

    for (int t = 0; t < T_DIM; t++) {
        // ---- prefetch t+1 (wait at chunk boundary only) ----
        const int tn = (t + 1 < T_DIM) ? (t + 1) : t;
        if (tn != t && (tn & 7) == 0) wait_chunk(tn >> 3);
        const float* pn = g_kvqm + (size_t)tn * (B_DIM * C_DIM) + b * C_DIM;
        float2 nk = ((const float2*)(pn      ))[lane];
        float2 nq = ((const float2*)(pn + 128))[lane];
        float2 nm = ((const float2*)(pn + 192))[lane];
        float  nv = pn[64 + i];

        // ---- S gate: G_S = sigmoid(v_i*k_j + B_S) ----
        float vk0 = v * k2.x, vk1 = v * k2.y;
        float x0 = fmaxf(vk0 + bs2.x, -30.0f);
        float x1 = fmaxf(vk1 + bs2.y, -30.0f);
        float e0 = __expf(-x0), e1 = __expf(-x1);
        float d0 = 1.0f + e0,   d1 = 1.0f + e1;
        float r  = __fdividef(1.0f, d0 * d1);   // 1 RCP serves 2 sigmoids
        float g0 = r * d1,      g1 = r * d0;
        s.x = fmaf(g0, s.x - vk0, vk0);
        s.y = fmaf(g1, s.y - vk1, vk1);

        // ---- Sq = S @ q (warp allreduce over 64 cols) ----
        float Sq = warp_sum(fmaf(s.x, q2.x, s.y * q2.y));

        // ---- M gate ----
        float sm0 = Sq * m2.x, sm1 = Sq * m2.y;
        float y0 = fmaxf(sm0 + bm2.x, -30.0f);
        float y1 = fmaxf(sm1 + bm2.y, -30.0f);
        float f0 = __expf(-y0), f1 = __expf(-y1);
        float c0 = 1.0f + f0,   c1 = 1.0f + f1;
        float rr = __fdividef(1.0f, c0 * c1);
        float h0 = rr * c1,     h1 = rr * c0;
        ms.x = fmaf(h0, ms.x - sm0, sm0);
        ms.y = fmaf(h1, ms.y - sm1, sm1);

        // ---- out = M @ q ----
        float o = warp_sum(fmaf(ms.x, q2.x, ms.y * q2.y));
        if (lane == 0)
            out[(size_t)(t * B_DIM + b) * N_DIM + i] = o;

        k2 = nk; q2 = nq; m2 = nm; v = nv;
    }

    // Final states S_f, M_f packed after outs
    const int OUTS = T_DIM * B_DIM * N_DIM;
    const int STN  = B_DIM * N_DIM * N_DIM;
    if (out_size >= OUTS + 2 * STN) {
        ((float2*)(out + OUTS + (size_t)row * N_DIM))[lane]       = s;
        ((float2*)(out + OUTS + STN + (size_t)row * N_DIM))[lane] = ms;
    }
}

// ---------------------------------------------------------------------------
// Launch
// ---------------------------------------------------------------------------
extern "C" void kernel_launch(void* const* d_in, const int* in_sizes, int n_in,
                              void* d_out, int out_size) {
    const float* x   = (const float*)d_in[0];   // (T, B, D)
    const float* S0  = (const float*)d_in[1];   // (B, N, N)
    const float* M0  = (const float*)d_in[2];   // (B, N, N)
    const float* W   = (const float*)d_in[3];   // (4N, D)
    const float* B_S = (const float*)d_in[4];   // (N, N)
    const float* B_M = (const float*)d_in[5];   // (N, N)
    float* out = (float*)d_out;

    e80_zero_flags<<<1, NUM_MTILES>>>();
    e80_fused<<<NUM_GEMM_CTAS + NUM_SCAN_CTAS, 256>>>(
        x, S0, M0, W, B_S, B_M, out, out_size);
}

// round 13
// speedup vs baseline: 1.0089x; 1.0088x over previous
#include <cuda_runtime.h>

// Problem dims
#define T_DIM 2048
#define B_DIM 16
#define D_DIM 1024
#define N_DIM 64
#define C_DIM 256   // 4*N

#define NUM_GEMM_CTAS 168
#define NUM_SCAN_CTAS 128
#define NUM_MTILES    256          // (T*B)/128 m-tiles; each = 8 timesteps
#define NUM_TILES     512          // 256 m-tiles x 2 n-tiles

// 32 MB scratch for projected k/v/q/m: (T, B, 4N)
__device__ float g_kvqm[(size_t)T_DIM * B_DIM * C_DIM];
// Per-m-tile completion counters (2 = both n-tiles done)
__device__ int g_done[NUM_MTILES];

__global__ void e80_zero_flags() {
    g_done[threadIdx.x] = 0;
}

// ---------------------------------------------------------------------------
// GEMM tile body: computes one 128x128 tile of kvqm = X * W^T (NT, fp32).
// ---------------------------------------------------------------------------
__device__ __forceinline__ void gemm_tile(const float* __restrict__ A,
                                          const float* __restrict__ W,
                                          int mBase, int nBase,
                                          float (*As)[128], float (*Bs)[128]) {
    const int K  = D_DIM;
    const int tid = threadIdx.x;
    const int lr = tid >> 2;          // 0..63 (and +64)
    const int kq = (tid & 3) * 4;     // 0,4,8,12

    const float* Ag = A + (size_t)(mBase + lr) * K + kq;
    const float* Wg = W + (size_t)(nBase + lr) * K + kq;

    float4 pa0 = *(const float4*)(Ag);
    float4 pa1 = *(const float4*)(Ag + (size_t)64 * K);
    float4 pb0 = *(const float4*)(Wg);
    float4 pb1 = *(const float4*)(Wg + (size_t)64 * K);

    const int tx = tid & 15;
    const int ty = tid >> 4;

    float acc[8][8];
#pragma unroll
    for (int i = 0; i < 8; i++)
#pragma unroll
        for (int j = 0; j < 8; j++) acc[i][j] = 0.0f;

    for (int k0 = 0; k0 < K; k0 += 16) {
        As[kq + 0][lr] = pa0.x; As[kq + 1][lr] = pa0.y;
        As[kq + 2][lr] = pa0.z; As[kq + 3][lr] = pa0.w;
        As[kq + 0][lr + 64] = pa1.x; As[kq + 1][lr + 64] = pa1.y;
        As[kq + 2][lr + 64] = pa1.z; As[kq + 3][lr + 64] = pa1.w;
        Bs[kq + 0][lr] = pb0.x; Bs[kq + 1][lr] = pb0.y;
        Bs[kq + 2][lr] = pb0.z; Bs[kq + 3][lr] = pb0.w;
        Bs[kq + 0][lr + 64] = pb1.x; Bs[kq + 1][lr + 64] = pb1.y;
        Bs[kq + 2][lr + 64] = pb1.z; Bs[kq + 3][lr + 64] = pb1.w;
        __syncthreads();

        if (k0 + 16 < K) {
            pa0 = *(const float4*)(Ag + k0 + 16);
            pa1 = *(const float4*)(Ag + (size_t)64 * K + k0 + 16);
            pb0 = *(const float4*)(Wg + k0 + 16);
            pb1 = *(const float4*)(Wg + (size_t)64 * K + k0 + 16);
        }

#pragma unroll
        for (int k = 0; k < 16; k++) {
            float ar[8], br[8];
            *(float4*)&ar[0] = *(const float4*)&As[k][ty * 8];
            *(float4*)&ar[4] = *(const float4*)&As[k][ty * 8 + 4];
            *(float4*)&br[0] = *(const float4*)&Bs[k][tx * 8];
            *(float4*)&br[4] = *(const float4*)&Bs[k][tx * 8 + 4];
#pragma unroll
            for (int i = 0; i < 8; i++)
#pragma unroll
                for (int j = 0; j < 8; j++)
                    acc[i][j] = fmaf(ar[i], br[j], acc[i][j]);
        }
        __syncthreads();
    }

#pragma unroll
    for (int i = 0; i < 8; i++) {
        float* Cp = g_kvqm + (size_t)(mBase + ty * 8 + i) * C_DIM + nBase + tx * 8;
        *(float4*)Cp       = make_float4(acc[i][0], acc[i][1], acc[i][2], acc[i][3]);
        *(float4*)(Cp + 4) = make_float4(acc[i][4], acc[i][5], acc[i][6], acc[i][7]);
    }
}

__device__ __forceinline__ float warp_sum(float p) {
#pragma unroll
    for (int off = 16; off > 0; off >>= 1)
        p += __shfl_xor_sync(0xffffffffu, p, off);
    return p;
}

// Consumer-side chunk wait (chunk m ready when both n-tiles committed).
__device__ __forceinline__ void wait_chunk(int m) {
    if (*(volatile int*)&g_done[m] < 2) {
        while (*(volatile int*)&g_done[m] < 2) __nanosleep(64);
    }
    __threadfence();   // acquire: order subsequent kvqm loads after flag
}

// ---------------------------------------------------------------------------
// Fused kernel: blocks [0, NUM_GEMM_CTAS) produce kvqm tiles in time order;
// blocks [NUM_GEMM_CTAS, +NUM_SCAN_CTAS) run the gated scan, consuming
// 8-timestep chunks as they become ready. Producers never wait on consumers,
// so the kernel is deadlock-free even if co-residency degrades.
// ---------------------------------------------------------------------------
__global__ __launch_bounds__(256, 2)
void e80_fused(const float* __restrict__ x,
               const float* __restrict__ S0,
               const float* __restrict__ M0,
               const float* __restrict__ W,
               const float* __restrict__ B_S,
               const float* __restrict__ B_M,
               float* __restrict__ out, int out_size) {
    __shared__ float As[16][128];
    __shared__ float Bs[16][128];

    if (blockIdx.x < NUM_GEMM_CTAS) {
        // ---------------- producer: persistent GEMM ----------------
        for (int L = blockIdx.x; L < NUM_TILES; L += NUM_GEMM_CTAS) {
            const int m = L >> 1;          // time-major: tiles ordered by m
            const int n = L & 1;
            gemm_tile(x, W, m * 128, n * 128, As, Bs);
            __threadfence();               // make tile stores visible (gpu scope)
            __syncthreads();               // all threads' stores + fences done
            if (threadIdx.x == 0) atomicAdd(&g_done[m], 1);
            __syncthreads();               // smem reuse safety for next tile
        }
        return;
    }

    // ---------------- consumer: gated two-level scan ----------------
    const int warp = threadIdx.x >> 5;
    const int lane = threadIdx.x & 31;
    const int row  = (blockIdx.x - NUM_GEMM_CTAS) * 8 + warp;   // 0..1023
    const int b    = row >> 6;
    const int i    = row & 63;

    float2 bs2 = ((const float2*)(B_S + i * N_DIM))[lane];
    float2 bm2 = ((const float2*)(B_M + i * N_DIM))[lane];
    float2 s   = ((const float2*)(S0 + (size_t)row * N_DIM))[lane];
    float2 ms  = ((const float2*)(M0 + (size_t)row * N_DIM))[lane];

    // Wait for chunk 0, then load t = 0 inputs
    wait_chunk(0);
    const float* p0 = g_kvqm + b * C_DIM;
    float2 k2 = ((const float2*)(p0      ))[lane];
    float2 q2 = ((const float2*)(p0 + 128))[lane];
    float2 m2 = ((const float2*)(p0 + 192))[lane];
    float  v  = p0[64 + i];

    for (int t = 0; t < T_DIM; t++) {
        // ---- prefetch t+1 (wait at chunk boundary only) ----
        const int tn = (t + 1 < T_DIM) ? (t + 1) : t;
        if (tn != t && (tn & 7) == 0) wait_chunk(tn >> 3);
        const float* pn = g_kvqm + (size_t)tn * (B_DIM * C_DIM) + b * C_DIM;
        float2 nk = ((const float2*)(pn      ))[lane];
        float2 nq = ((const float2*)(pn + 128))[lane];
        float2 nm = ((const float2*)(pn + 192))[lane];
        float  nv = pn[64 + i];

        // ---- S gate: G_S = sigmoid(v_i*k_j + B_S) ----
        float vk0 = v * k2.x, vk1 = v * k2.y;
        float x0 = fmaxf(vk0 + bs2.x, -30.0f);
        float x1 = fmaxf(vk1 + bs2.y, -30.0f);
        float e0 = __expf(-x0), e1 = __expf(-x1);
        float d0 = 1.0f + e0,   d1 = 1.0f + e1;
        float r  = __fdividef(1.0f, d0 * d1);   // 1 RCP serves 2 sigmoids
        float g0 = r * d1,      g1 = r * d0;
        s.x = fmaf(g0, s.x - vk0, vk0);
        s.y = fmaf(g1, s.y - vk1, vk1);

        // ---- Sq = S @ q (warp allreduce over 64 cols) ----
        float Sq = warp_sum(fmaf(s.x, q2.x, s.y * q2.y));

        // ---- M gate ----
        float sm0 = Sq * m2.x, sm1 = Sq * m2.y;
        float y0 = fmaxf(sm0 + bm2.x, -30.0f);
        float y1 = fmaxf(sm1 + bm2.y, -30.0f);
        float f0 = __expf(-y0), f1 = __expf(-y1);
        float c0 = 1.0f + f0,   c1 = 1.0f + f1;
        float rr = __fdividef(1.0f, c0 * c1);
        float h0 = rr * c1,     h1 = rr * c0;
        ms.x = fmaf(h0, ms.x - sm0, sm0);
        ms.y = fmaf(h1, ms.y - sm1, sm1);

        // ---- out = M @ q ----
        float o = warp_sum(fmaf(ms.x, q2.x, ms.y * q2.y));
        if (lane == 0)
            out[(size_t)(t * B_DIM + b) * N_DIM + i] = o;

        k2 = nk; q2 = nq; m2 = nm; v = nv;
    }

    // Final states S_f, M_f packed after outs
    const int OUTS = T_DIM * B_DIM * N_DIM;
    const int STN  = B_DIM * N_DIM * N_DIM;
    if (out_size >= OUTS + 2 * STN) {
        ((float2*)(out + OUTS + (size_t)row * N_DIM))[lane]       = s;
        ((float2*)(out + OUTS + STN + (size_t)row * N_DIM))[lane] = ms;
    }
}

// ---------------------------------------------------------------------------
// Launch
// ---------------------------------------------------------------------------
extern "C" void kernel_launch(void* const* d_in, const int* in_sizes, int n_in,
                              void* d_out, int out_size) {
    const float* x   = (const float*)d_in[0];   // (T, B, D)
    const float* S0  = (const float*)d_in[1];   // (B, N, N)
    const float* M0  = (const float*)d_in[2];   // (B, N, N)
    const float* W   = (const float*)d_in[3];   // (4N, D)
    const float* B_S = (const float*)d_in[4];   // (N, N)
    const float* B_M = (const float*)d_in[5];   // (N, N)
    float* out = (float*)d_out;

    e80_zero_flags<<<1, NUM_MTILES>>>();
    e80_fused<<<NUM_GEMM_CTAS + NUM_SCAN_CTAS, 256>>>(
        x, S0, M0, W, B_S, B_M, out, out_size);
}

// round 14
// speedup vs baseline: 1.7051x; 1.6899x over previous
#include <cuda_runtime.h>

// Problem dims
#define T_DIM 2048
#define B_DIM 16
#define D_DIM 1024
#define N_DIM 64
#define C_DIM 256   // 4*N

#define NUM_GEMM_CTAS 168
#define NUM_SCAN_CTAS 128
#define NUM_MTILES    256          // (T*B)/128 m-tiles; each = 8 timesteps
#define NUM_TILES     512          // 256 m-tiles x 2 n-tiles
#define STEPS_PER_CHUNK 8

// 32 MB scratch for projected k/v/q/m: (T, B, 4N)
__device__ float g_kvqm[(size_t)T_DIM * B_DIM * C_DIM];
// Per-m-tile completion counters (2 = both n-tiles done)
__device__ int g_done[NUM_MTILES];

__global__ void e80_zero_flags() {
    g_done[threadIdx.x] = 0;
}

// ---------------------------------------------------------------------------
// GEMM tile body: one 128x128 tile of kvqm = X * W^T (NT, fp32).
// ---------------------------------------------------------------------------
__device__ __forceinline__ void gemm_tile(const float* __restrict__ A,
                                          const float* __restrict__ W,
                                          int mBase, int nBase,
                                          float (*As)[128], float (*Bs)[128]) {
    const int K  = D_DIM;
    const int tid = threadIdx.x;
    const int lr = tid >> 2;          // 0..63 (and +64)
    const int kq = (tid & 3) * 4;     // 0,4,8,12

    const float* Ag = A + (size_t)(mBase + lr) * K + kq;
    const float* Wg = W + (size_t)(nBase + lr) * K + kq;

    float4 pa0 = *(const float4*)(Ag);
    float4 pa1 = *(const float4*)(Ag + (size_t)64 * K);
    float4 pb0 = *(const float4*)(Wg);
    float4 pb1 = *(const float4*)(Wg + (size_t)64 * K);

    const int tx = tid & 15;
    const int ty = tid >> 4;

    float acc[8][8];
#pragma unroll
    for (int i = 0; i < 8; i++)
#pragma unroll
        for (int j = 0; j < 8; j++) acc[i][j] = 0.0f;

    for (int k0 = 0; k0 < K; k0 += 16) {
        As[kq + 0][lr] = pa0.x; As[kq + 1][lr] = pa0.y;
        As[kq + 2][lr] = pa0.z; As[kq + 3][lr] = pa0.w;
        As[kq + 0][lr + 64] = pa1.x; As[kq + 1][lr + 64] = pa1.y;
        As[kq + 2][lr + 64] = pa1.z; As[kq + 3][lr + 64] = pa1.w;
        Bs[kq + 0][lr] = pb0.x; Bs[kq + 1][lr] = pb0.y;
        Bs[kq + 2][lr] = pb0.z; Bs[kq + 3][lr] = pb0.w;
        Bs[kq + 0][lr + 64] = pb1.x; Bs[kq + 1][lr + 64] = pb1.y;
        Bs[kq + 2][lr + 64] = pb1.z; Bs[kq + 3][lr + 64] = pb1.w;
        __syncthreads();

        if (k0 + 16 < K) {
            pa0 = *(const float4*)(Ag + k0 + 16);
            pa1 = *(const float4*)(Ag + (size_t)64 * K + k0 + 16);
            pb0 = *(const float4*)(Wg + k0 + 16);
            pb1 = *(const float4*)(Wg + (size_t)64 * K + k0 + 16);
        }

#pragma unroll
        for (int k = 0; k < 16; k++) {
            float ar[8], br[8];
            *(float4*)&ar[0] = *(const float4*)&As[k][ty * 8];
            *(float4*)&ar[4] = *(const float4*)&As[k][ty * 8 + 4];
            *(float4*)&br[0] = *(const float4*)&Bs[k][tx * 8];
            *(float4*)&br[4] = *(const float4*)&Bs[k][tx * 8 + 4];
#pragma unroll
            for (int i = 0; i < 8; i++)
#pragma unroll
                for (int j = 0; j < 8; j++)
                    acc[i][j] = fmaf(ar[i], br[j], acc[i][j]);
        }
        __syncthreads();
    }

#pragma unroll
    for (int i = 0; i < 8; i++) {
        float* Cp = g_kvqm + (size_t)(mBase + ty * 8 + i) * C_DIM + nBase + tx * 8;
        *(float4*)Cp       = make_float4(acc[i][0], acc[i][1], acc[i][2], acc[i][3]);
        *(float4*)(Cp + 4) = make_float4(acc[i][4], acc[i][5], acc[i][6], acc[i][7]);
    }
}

__device__ __forceinline__ float warp_sum(float p) {
#pragma unroll
    for (int off = 16; off > 0; off >>= 1)
        p += __shfl_xor_sync(0xffffffffu, p, off);
    return p;
}

// Consumer-side chunk wait (chunk m ready when both n-tiles committed).
__device__ __forceinline__ void wait_chunk(int m) {
    if (*(volatile int*)&g_done[m] < 2) {
        while (*(volatile int*)&g_done[m] < 2) __nanosleep(64);
    }
    __threadfence();   // acquire: order subsequent kvqm loads after flag
}

// ---------------------------------------------------------------------------
// Fused kernel. Producer CTAs stream kvqm tiles in time order; consumer CTAs
// run the gated scan in 8-step chunks: one wait + batched register loads per
// chunk, then a branch-free fully-unrolled compute block so ptxas can
// software-pipeline the SHFL reduce chains across steps.
// ---------------------------------------------------------------------------
__global__ __launch_bounds__(256, 2)
void e80_fused(const float* __restrict__ x,
               const float* __restrict__ S0,
               const float* __restrict__ M0,
               const float* __restrict__ W,
               const float* __restrict__ B_S,
               const float* __restrict__ B_M,
               float* __restrict__ out, int out_size) {
    __shared__ float As[16][128];
    __shared__ float Bs[16][128];

    if (blockIdx.x < NUM_GEMM_CTAS) {
        // ---------------- producer: persistent GEMM ----------------
        for (int L = blockIdx.x; L < NUM_TILES; L += NUM_GEMM_CTAS) {
            const int m = L >> 1;          // time-major tile order
            const int n = L & 1;
            gemm_tile(x, W, m * 128, n * 128, As, Bs);
            __threadfence();
            __syncthreads();
            if (threadIdx.x == 0) atomicAdd(&g_done[m], 1);
            __syncthreads();
        }
        return;
    }

    // ---------------- consumer: gated two-level scan ----------------
    const int warp = threadIdx.x >> 5;
    const int lane = threadIdx.x & 31;
    const int row  = (blockIdx.x - NUM_GEMM_CTAS) * 8 + warp;   // 0..1023
    const int b    = row >> 6;
    const int i    = row & 63;

    float2 bs2 = ((const float2*)(B_S + i * N_DIM))[lane];
    float2 bm2 = ((const float2*)(B_M + i * N_DIM))[lane];
    float2 s   = ((const float2*)(S0 + (size_t)row * N_DIM))[lane];
    float2 ms  = ((const float2*)(M0 + (size_t)row * N_DIM))[lane];

    float* outp = out + b * N_DIM + i;                 // lane-0 store base
    const float* basep = g_kvqm + b * C_DIM;

    for (int c = 0; c < NUM_MTILES; c++) {
        wait_chunk(c);

        // ---- batched loads for the whole 8-step chunk (high MLP) ----
        float2 kk[STEPS_PER_CHUNK], qq[STEPS_PER_CHUNK], mm[STEPS_PER_CHUNK];
        float  vv[STEPS_PER_CHUNK];
        const float* pc = basep + (size_t)c * STEPS_PER_CHUNK * (B_DIM * C_DIM);
#pragma unroll
        for (int u = 0; u < STEPS_PER_CHUNK; u++) {
            const float* p = pc + (size_t)u * (B_DIM * C_DIM);
            kk[u] = ((const float2*)(p      ))[lane];
            qq[u] = ((const float2*)(p + 128))[lane];
            mm[u] = ((const float2*)(p + 192))[lane];
            vv[u] = p[64 + i];
        }

        // ---- branch-free unrolled 8-step compute ----
#pragma unroll
        for (int u = 0; u < STEPS_PER_CHUNK; u++) {
            const float v = vv[u];
            const float2 k2 = kk[u], q2 = qq[u], m2 = mm[u];

            // S gate: G_S = sigmoid(v_i*k_j + B_S)
            float vk0 = v * k2.x, vk1 = v * k2.y;
            float x0 = fmaxf(vk0 + bs2.x, -30.0f);
            float x1 = fmaxf(vk1 + bs2.y, -30.0f);
            float e0 = __expf(-x0), e1 = __expf(-x1);
            float d0 = 1.0f + e0,   d1 = 1.0f + e1;
            float r  = __fdividef(1.0f, d0 * d1);   // 1 RCP, 2 sigmoids
            float g0 = r * d1,      g1 = r * d0;
            s.x = fmaf(g0, s.x - vk0, vk0);
            s.y = fmaf(g1, s.y - vk1, vk1);

            // Sq = S @ q  (warp allreduce over 64 cols)
            float Sq = warp_sum(fmaf(s.x, q2.x, s.y * q2.y));

            // M gate
            float sm0 = Sq * m2.x, sm1 = Sq * m2.y;
            float y0 = fmaxf(sm0 + bm2.x, -30.0f);
            float y1 = fmaxf(sm1 + bm2.y, -30.0f);
            float f0 = __expf(-y0), f1 = __expf(-y1);
            float c0 = 1.0f + f0,   c1 = 1.0f + f1;
            float rr = __fdividef(1.0f, c0 * c1);
            float h0 = rr * c1,     h1 = rr * c0;
            ms.x = fmaf(h0, ms.x - sm0, sm0);
            ms.y = fmaf(h1, ms.y - sm1, sm1);

            // out = M @ q  (off the carried dependency; pipelines freely)
            float o = warp_sum(fmaf(ms.x, q2.x, ms.y * q2.y));
            if (lane == 0)
                outp[(size_t)(c * STEPS_PER_CHUNK + u) * (B_DIM * N_DIM)] = o;
        }
    }

    // Final states S_f, M_f packed after outs
    const int OUTS = T_DIM * B_DIM * N_DIM;
    const int STN  = B_DIM * N_DIM * N_DIM;
    if (out_size >= OUTS + 2 * STN) {
        ((float2*)(out + OUTS + (size_t)row * N_DIM))[lane]       = s;
        ((float2*)(out + OUTS + STN + (size_t)row * N_DIM))[lane] = ms;
    }
}

// ---------------------------------------------------------------------------
// Launch
// ---------------------------------------------------------------------------
extern "C" void kernel_launch(void* const* d_in, const int* in_sizes, int n_in,
                              void* d_out, int out_size) {
    const float* x   = (const float*)d_in[0];   // (T, B, D)
    const float* S0  = (const float*)d_in[1];   // (B, N, N)
    const float* M0  = (const float*)d_in[2];   // (B, N, N)
    const float* W   = (const float*)d_in[3];   // (4N, D)
    const float* B_S = (const float*)d_in[4];   // (N, N)
    const float* B_M = (const float*)d_in[5];   // (N, N)
    float* out = (float*)d_out;

    e80_zero_flags<<<1, NUM_MTILES>>>();
    e80_fused<<<NUM_GEMM_CTAS + NUM_SCAN_CTAS, 256>>>(
        x, S0, M0, W, B_S, B_M, out, out_size);
}